// round 5
// baseline (speedup 1.0000x reference)
#include <cuda_runtime.h>

// Problem constants
#define Bn    2
#define Sn    2048
#define En    1024
#define Hn    16
#define DHn   64
#define KSn   3
#define TCONV 512

// ---------------------------------------------------------------------------
// Scratch (device globals; no runtime allocation allowed)
// ---------------------------------------------------------------------------
__device__ float g_Q  [(size_t)Bn * Sn * En];       // 16 MB, [b*S+s][E]
__device__ float g_K  [(size_t)Bn * Sn * En];       // 16 MB
__device__ float g_V  [(size_t)Bn * Sn * En];       // 16 MB
__device__ float g_ctx[(size_t)Bn * Sn * En];       // 16 MB, attention output pre-Wo
__device__ float g_S  [(size_t)Bn * Hn * Sn * Sn];  // 512 MB, raw scores [bh][q][k]
__device__ float g_S2 [(size_t)Bn * Hn * Sn * Sn];  // 512 MB, conv scores / weights

// ---------------------------------------------------------------------------
// 128x128x16 fp32 NT GEMM tile:  C[m,n] = alpha * sum_k A[m,k]*B[n,k] + bias[n]
// A: [128 rows, K] row-major (lda), B: [128 rows(n), K] row-major (ldb).
// 256 threads, each computes 8x8. Register prefetch of next K-tile.
// ---------------------------------------------------------------------------
__device__ __forceinline__ void sgemm_nt_128x128(
    const float* __restrict__ A, int lda,
    const float* __restrict__ B, int ldb,
    float* __restrict__ C, int ldc,
    int K, float alpha, const float* __restrict__ bias)
{
    __shared__ float As[16][128];
    __shared__ float Bs[16][128];

    const int tid = threadIdx.x;
    const int tx  = tid & 15;          // 0..15 -> n micro
    const int ty  = tid >> 4;          // 0..15 -> m micro
    const int lr  = tid >> 2;          // 0..63 loader row
    const int lc  = (tid & 3) << 2;    // 0,4,8,12 loader k-col

    float acc[8][8];
#pragma unroll
    for (int i = 0; i < 8; ++i)
#pragma unroll
        for (int j = 0; j < 8; ++j) acc[i][j] = 0.f;

    const float* Ap0 = A + (size_t)lr * lda + lc;
    const float* Ap1 = A + (size_t)(lr + 64) * lda + lc;
    const float* Bp0 = B + (size_t)lr * ldb + lc;
    const float* Bp1 = B + (size_t)(lr + 64) * ldb + lc;

    float4 a0 = *(const float4*)(Ap0);
    float4 a1 = *(const float4*)(Ap1);
    float4 b0 = *(const float4*)(Bp0);
    float4 b1 = *(const float4*)(Bp1);

    for (int k0 = 0; k0 < K; k0 += 16) {
        __syncthreads();
        As[lc + 0][lr]      = a0.x; As[lc + 1][lr]      = a0.y;
        As[lc + 2][lr]      = a0.z; As[lc + 3][lr]      = a0.w;
        As[lc + 0][lr + 64] = a1.x; As[lc + 1][lr + 64] = a1.y;
        As[lc + 2][lr + 64] = a1.z; As[lc + 3][lr + 64] = a1.w;
        Bs[lc + 0][lr]      = b0.x; Bs[lc + 1][lr]      = b0.y;
        Bs[lc + 2][lr]      = b0.z; Bs[lc + 3][lr]      = b0.w;
        Bs[lc + 0][lr + 64] = b1.x; Bs[lc + 1][lr + 64] = b1.y;
        Bs[lc + 2][lr + 64] = b1.z; Bs[lc + 3][lr + 64] = b1.w;
        __syncthreads();

        if (k0 + 16 < K) {   // prefetch next K-tile into registers
            a0 = *(const float4*)(Ap0 + k0 + 16);
            a1 = *(const float4*)(Ap1 + k0 + 16);
            b0 = *(const float4*)(Bp0 + k0 + 16);
            b1 = *(const float4*)(Bp1 + k0 + 16);
        }

#pragma unroll
        for (int k = 0; k < 16; ++k) {
            float4 arl = *(const float4*)&As[k][ty * 8];
            float4 arh = *(const float4*)&As[k][ty * 8 + 4];
            float4 brl = *(const float4*)&Bs[k][tx * 8];
            float4 brh = *(const float4*)&Bs[k][tx * 8 + 4];
            float ar[8] = {arl.x, arl.y, arl.z, arl.w, arh.x, arh.y, arh.z, arh.w};
            float br[8] = {brl.x, brl.y, brl.z, brl.w, brh.x, brh.y, brh.z, brh.w};
#pragma unroll
            for (int i = 0; i < 8; ++i)
#pragma unroll
                for (int j = 0; j < 8; ++j)
                    acc[i][j] = fmaf(ar[i], br[j], acc[i][j]);
        }
    }

    float bv[8];
    if (bias) {
#pragma unroll
        for (int j = 0; j < 8; ++j) bv[j] = bias[tx * 8 + j];
    } else {
#pragma unroll
        for (int j = 0; j < 8; ++j) bv[j] = 0.f;
    }
#pragma unroll
    for (int i = 0; i < 8; ++i) {
        float o[8];
#pragma unroll
        for (int j = 0; j < 8; ++j) o[j] = fmaf(acc[i][j], alpha, bv[j]);
        float* cp = C + (size_t)(ty * 8 + i) * ldc + tx * 8;
        *(float4*)(cp)     = make_float4(o[0], o[1], o[2], o[3]);
        *(float4*)(cp + 4) = make_float4(o[4], o[5], o[6], o[7]);
    }
}

// ---------------------------------------------------------------------------
// Kernel 1: fused QKV projection.  grid (E/128, B*S/128, 3)
// out[m,n] = query[m,:] . W[n,:] + b[n]   (out = query @ W^T + b)
// ---------------------------------------------------------------------------
__global__ void __launch_bounds__(256)
qkv_kernel(const float* __restrict__ query,
           const float* __restrict__ Wq, const float* __restrict__ bq,
           const float* __restrict__ Wk, const float* __restrict__ bk,
           const float* __restrict__ Wv, const float* __restrict__ bv)
{
    const int z = blockIdx.z;
    const float* W  = (z == 0) ? Wq : ((z == 1) ? Wk : Wv);
    const float* bi = (z == 0) ? bq : ((z == 1) ? bk : bv);
    float* Cb       = (z == 0) ? g_Q : ((z == 1) ? g_K : g_V);

    const float* A = query + (size_t)blockIdx.y * 128 * En;
    const float* B = W     + (size_t)blockIdx.x * 128 * En;
    float*       C = Cb    + (size_t)blockIdx.y * 128 * En + blockIdx.x * 128;
    sgemm_nt_128x128(A, En, B, En, C, En, En, 1.0f, bi + blockIdx.x * 128);
}

// ---------------------------------------------------------------------------
// Kernel 2: scores = Q Kᵀ / 8 per (b,h).  grid (S/128, S/128, B*H)
// ---------------------------------------------------------------------------
__global__ void __launch_bounds__(256)
scores_kernel()
{
    const int bh = blockIdx.z;
    const int b = bh >> 4, h = bh & 15;
    const float* A = g_Q + ((size_t)b * Sn + blockIdx.y * 128) * En + h * DHn;
    const float* B = g_K + ((size_t)b * Sn + blockIdx.x * 128) * En + h * DHn;
    float*       C = g_S + (size_t)bh * Sn * Sn
                         + (size_t)blockIdx.y * 128 * Sn + blockIdx.x * 128;
    sgemm_nt_128x128(A, En, B, En, C, Sn, DHn, 0.125f, nullptr);
}

// ---------------------------------------------------------------------------
// Kernel 3: cross-head conv1d along key axis (NCW, OIW, pad=1).
// out[b,h,q,k] = cb[h] + sum_{h2,t} w[h,h2,t] * scores[b,h2,q,k+t-1]
// One CTA per (b, q, k-tile of 512). Per-thread: fixed output head h,
// contiguous 32-k chunk; h2 loop staggered by lane so the 16 same-h lanes
// (k-chunks all == 0 mod 32 banks) hit 16 distinct smem rows -> no conflicts.
// ---------------------------------------------------------------------------
__global__ void __launch_bounds__(256)
conv_kernel(const float* __restrict__ w, const float* __restrict__ cb)
{
    __shared__ float sm[Hn][TCONV + 2];
    __shared__ float ws[Hn * Hn * KSn];
    __shared__ float cbs[Hn];

    const int tid = threadIdx.x;
    const int b = blockIdx.z, q = blockIdx.y;
    const int k0 = blockIdx.x * TCONV;

    for (int i = tid; i < Hn * Hn * KSn; i += 256) ws[i] = w[i];
    if (tid < Hn) cbs[tid] = cb[tid];

    for (int i = tid; i < Hn * (TCONV + 2); i += 256) {
        const int h = i / (TCONV + 2);
        const int j = i - h * (TCONV + 2);
        const int k = k0 - 1 + j;
        float v = 0.f;
        if ((unsigned)k < (unsigned)Sn)
            v = g_S[(((size_t)(b * Hn + h) * Sn + q) * Sn) + k];
        sm[h][j] = v;
    }
    __syncthreads();

    const int h   = tid >> 4;
    const int t15 = tid & 15;
    const int kb  = t15 * 32;

    float acc[32];
    const float c0 = cbs[h];
#pragma unroll
    for (int i = 0; i < 32; ++i) acc[i] = c0;

#pragma unroll 1
    for (int hh = 0; hh < Hn; ++hh) {
        const int h2 = (hh + t15) & 15;           // lane-staggered input head
        const float w0 = ws[(h * Hn + h2) * KSn + 0];
        const float w1 = ws[(h * Hn + h2) * KSn + 1];
        const float w2 = ws[(h * Hn + h2) * KSn + 2];
        float r0 = sm[h2][kb + 0];
        float r1 = sm[h2][kb + 1];
#pragma unroll
        for (int i = 0; i < 32; ++i) {
            const float r2 = sm[h2][kb + i + 2];
            acc[i] = fmaf(w0, r0, acc[i]);
            acc[i] = fmaf(w1, r1, acc[i]);
            acc[i] = fmaf(w2, r2, acc[i]);
            r0 = r1; r1 = r2;
        }
    }

    const size_t obase = (((size_t)(b * Hn + h) * Sn + q) * Sn) + k0 + kb;
#pragma unroll
    for (int i = 0; i < 32; i += 4)
        *(float4*)(g_S2 + obase + i) =
            make_float4(acc[i], acc[i + 1], acc[i + 2], acc[i + 3]);
}

// ---------------------------------------------------------------------------
// Kernel 4: row softmax in place on g_S2. One CTA per (b,h,q) row of 2048.
// Fully register-resident: 8 floats/thread, two block reductions.
// ---------------------------------------------------------------------------
__global__ void __launch_bounds__(256)
softmax_kernel()
{
    __shared__ float redm[8];
    __shared__ float reds[8];
    const int tid = threadIdx.x;
    float4* p = (float4*)(g_S2 + (size_t)blockIdx.x * Sn);

    float4 x0 = p[tid];
    float4 x1 = p[tid + 256];

    float m = fmaxf(fmaxf(fmaxf(x0.x, x0.y), fmaxf(x0.z, x0.w)),
                    fmaxf(fmaxf(x1.x, x1.y), fmaxf(x1.z, x1.w)));
#pragma unroll
    for (int o = 16; o > 0; o >>= 1)
        m = fmaxf(m, __shfl_xor_sync(0xffffffffu, m, o));
    if ((tid & 31) == 0) redm[tid >> 5] = m;
    __syncthreads();
    float mm = redm[0];
#pragma unroll
    for (int i = 1; i < 8; ++i) mm = fmaxf(mm, redm[i]);

    float e[8];
    e[0] = __expf(x0.x - mm); e[1] = __expf(x0.y - mm);
    e[2] = __expf(x0.z - mm); e[3] = __expf(x0.w - mm);
    e[4] = __expf(x1.x - mm); e[5] = __expf(x1.y - mm);
    e[6] = __expf(x1.z - mm); e[7] = __expf(x1.w - mm);

    float s = ((e[0] + e[1]) + (e[2] + e[3])) + ((e[4] + e[5]) + (e[6] + e[7]));
#pragma unroll
    for (int o = 16; o > 0; o >>= 1)
        s += __shfl_xor_sync(0xffffffffu, s, o);
    if ((tid & 31) == 0) reds[tid >> 5] = s;
    __syncthreads();
    float ss = reds[0];
#pragma unroll
    for (int i = 1; i < 8; ++i) ss += reds[i];

    const float inv = 1.0f / ss;
    x0 = make_float4(e[0] * inv, e[1] * inv, e[2] * inv, e[3] * inv);
    x1 = make_float4(e[4] * inv, e[5] * inv, e[6] * inv, e[7] * inv);
    p[tid]       = x0;
    p[tid + 256] = x1;
}

// ---------------------------------------------------------------------------
// Kernel 5: PV NN GEMM per (b,h): ctx[q, h*64+d] = sum_k W[q,k] * V[k, h*64+d]
// 128(M) x 64(N) x 16(K) tiles, 256 threads, each 8x4. grid (S/128, B*H)
// ---------------------------------------------------------------------------
__global__ void __launch_bounds__(256)
pv_kernel()
{
    const int bh = blockIdx.y;
    const int b = bh >> 4, h = bh & 15;
    const float* A  = g_S2 + (size_t)bh * Sn * Sn + (size_t)blockIdx.x * 128 * Sn;
    const float* Bp = g_V  + (size_t)b * Sn * En + h * DHn;
    float*       C  = g_ctx + (size_t)b * Sn * En
                            + (size_t)blockIdx.x * 128 * En + h * DHn;

    __shared__ float As[16][128];
    __shared__ float Bs[16][64];

    const int tid = threadIdx.x;
    const int tx = tid & 15, ty = tid >> 4;
    const int lr = tid >> 2, lc = (tid & 3) << 2;
    const int bk = tid >> 4, bn = (tid & 15) << 2;

    float acc[8][4];
#pragma unroll
    for (int i = 0; i < 8; ++i)
#pragma unroll
        for (int j = 0; j < 4; ++j) acc[i][j] = 0.f;

    const float* Ap0 = A  + (size_t)lr * Sn + lc;
    const float* Ap1 = A  + (size_t)(lr + 64) * Sn + lc;
    const float* Bpp = Bp + (size_t)bk * En + bn;

    float4 a0 = *(const float4*)(Ap0);
    float4 a1 = *(const float4*)(Ap1);
    float4 bb = *(const float4*)(Bpp);

    for (int k0 = 0; k0 < Sn; k0 += 16) {
        __syncthreads();
        As[lc + 0][lr]      = a0.x; As[lc + 1][lr]      = a0.y;
        As[lc + 2][lr]      = a0.z; As[lc + 3][lr]      = a0.w;
        As[lc + 0][lr + 64] = a1.x; As[lc + 1][lr + 64] = a1.y;
        As[lc + 2][lr + 64] = a1.z; As[lc + 3][lr + 64] = a1.w;
        *(float4*)&Bs[bk][bn] = bb;
        __syncthreads();

        if (k0 + 16 < Sn) {
            a0 = *(const float4*)(Ap0 + k0 + 16);
            a1 = *(const float4*)(Ap1 + k0 + 16);
            bb = *(const float4*)(Bpp + (size_t)(k0 + 16) * En);
        }

#pragma unroll
        for (int k = 0; k < 16; ++k) {
            float4 arl = *(const float4*)&As[k][ty * 8];
            float4 arh = *(const float4*)&As[k][ty * 8 + 4];
            float4 br4 = *(const float4*)&Bs[k][tx * 4];
            float ar[8] = {arl.x, arl.y, arl.z, arl.w, arh.x, arh.y, arh.z, arh.w};
            float br[4] = {br4.x, br4.y, br4.z, br4.w};
#pragma unroll
            for (int i = 0; i < 8; ++i)
#pragma unroll
                for (int j = 0; j < 4; ++j)
                    acc[i][j] = fmaf(ar[i], br[j], acc[i][j]);
        }
    }

#pragma unroll
    for (int i = 0; i < 8; ++i) {
        float* cp = C + (size_t)(ty * 8 + i) * En + tx * 4;
        *(float4*)cp = make_float4(acc[i][0], acc[i][1], acc[i][2], acc[i][3]);
    }
}

// ---------------------------------------------------------------------------
// Kernel 6: output projection: out = ctx @ Wo^T + bo.  grid (E/128, B*S/128)
// ---------------------------------------------------------------------------
__global__ void __launch_bounds__(256)
oproj_kernel(const float* __restrict__ Wo, const float* __restrict__ bo,
             float* __restrict__ out)
{
    const float* A = g_ctx + (size_t)blockIdx.y * 128 * En;
    const float* B = Wo    + (size_t)blockIdx.x * 128 * En;
    float*       C = out   + (size_t)blockIdx.y * 128 * En + blockIdx.x * 128;
    sgemm_nt_128x128(A, En, B, En, C, En, En, 1.0f, bo + blockIdx.x * 128);
}

// ---------------------------------------------------------------------------
// Launch
// ---------------------------------------------------------------------------
extern "C" void kernel_launch(void* const* d_in, const int* in_sizes, int n_in,
                              void* d_out, int out_size)
{
    (void)in_sizes; (void)n_in; (void)out_size;
    const float* query  = (const float*)d_in[0];
    const float* Wq     = (const float*)d_in[1];
    const float* bq     = (const float*)d_in[2];
    const float* Wk     = (const float*)d_in[3];
    const float* bk     = (const float*)d_in[4];
    const float* Wv     = (const float*)d_in[5];
    const float* bv     = (const float*)d_in[6];
    const float* Wo     = (const float*)d_in[7];
    const float* bo     = (const float*)d_in[8];
    const float* conv_w = (const float*)d_in[9];
    const float* conv_b = (const float*)d_in[10];
    float* out = (float*)d_out;

    qkv_kernel   <<<dim3(En / 128, (Bn * Sn) / 128, 3), 256>>>(query, Wq, bq, Wk, bk, Wv, bv);
    scores_kernel<<<dim3(Sn / 128, Sn / 128, Bn * Hn), 256>>>();
    conv_kernel  <<<dim3(Sn / TCONV, Sn, Bn), 256>>>(conv_w, conv_b);
    softmax_kernel<<<Bn * Hn * Sn, 256>>>();
    pv_kernel    <<<dim3(Sn / 128, Bn * Hn), 256>>>();
    oproj_kernel <<<dim3(En / 128, (Bn * Sn) / 128), 256>>>(Wo, bo, out);
}